// round 16
// baseline (speedup 1.0000x reference)
#include <cuda_runtime.h>
#include <cstdint>

#define Nn   50000
#define Cc   128
#define Emax 600000
#define ALPHAc 0.1f
#define BNEPS 1e-5f

// ---------------- packed dual-fp32 FMA (Blackwell f32x2; FMA pipe, NOT tensor) ------
#define FFMA2(d, a, b) \
    asm("fma.rn.f32x2 %0, %1, %2, %0;" : "+l"(d) : "l"(a), "l"(b))
#define PACK_DUP(d, xu) \
    asm("mov.b64 %0, {%1, %1};" : "=l"(d) : "r"(xu))

// ---------------- static device scratch (no allocations allowed) ----------------
__device__ int   g_deg[Nn];
__device__ float g_degf[Nn];
__device__ int   g_rowptr[Nn + 1];
__device__ int   g_cursor[Nn];
__device__ int   g_csr[Emax];
__device__ float g_state0[Nn * Cc];
__device__ float g_state1[Nn * Cc];
__device__ float g_A [5 * Nn * Cc];   // cached agg_mean per state 0..4
__device__ float g_Mx[5 * Nn * Cc];   // cached agg_max  per state 0..4
__device__ float g_acc[Nn * Cc];      // per-step elementwise accumulator
__device__ float g_h  [Nn * Cc];      // preprocess GEMM output
__device__ float g_Wstack[6 * Cc * Cc];
__device__ float g_stats[2 * Cc];     // col sums / sumsq
__device__ float g_scale[Cc];
__device__ float g_shift[Cc];

// ---------------- small helpers ----------------
__device__ __forceinline__ const float* state_ptr(int j, const float* out, int& ld) {
    if (j == 0) { ld = Cc; return g_state0; }
    if (j == 1) { ld = Cc; return g_state1; }
    ld = 4 * Cc;
    return out + (size_t)(j - 2) * Cc;   // states 2..5 live in d_out columns
}

// ---------------- CSR build ----------------
__global__ void k_zero_deg() {
    int i = blockIdx.x * blockDim.x + threadIdx.x;
    if (i < Nn) g_deg[i] = 0;
}

__global__ void k_hist(const int* __restrict__ dst, int E) {
    int i = blockIdx.x * blockDim.x + threadIdx.x;
    if (i < E) atomicAdd(&g_deg[dst[i]], 1);
}

__global__ void k_scan() {
    __shared__ int sh[1024];
    __shared__ int base;
    int t = threadIdx.x;
    if (t == 0) { base = 0; g_rowptr[0] = 0; }
    __syncthreads();
    for (int start = 0; start < Nn; start += 1024) {
        int i = start + t;
        int d = (i < Nn) ? g_deg[i] : 0;
        sh[t] = d;
        __syncthreads();
        for (int off = 1; off < 1024; off <<= 1) {
            int u = (t >= off) ? sh[t - off] : 0;
            __syncthreads();
            sh[t] += u;
            __syncthreads();
        }
        if (i < Nn) {
            int incl = sh[t];
            g_rowptr[i + 1] = base + incl;
            g_cursor[i]     = base + incl - d;
            g_degf[i]       = (float)(d > 1 ? d : 1);
        }
        __syncthreads();
        if (t == 0) base += sh[1023];
        __syncthreads();
    }
}

__global__ void k_fill(const int* __restrict__ src, const int* __restrict__ dst, int E) {
    int i = blockIdx.x * blockDim.x + threadIdx.x;
    if (i < E) {
        int p = atomicAdd(&g_cursor[dst[i]], 1);
        g_csr[p] = src[i];
    }
}

// ---------------- batch-norm stats / apply ----------------
__global__ void k_zero_stats() {
    int i = threadIdx.x;
    if (i < 2 * Cc) g_stats[i] = 0.f;
}

__global__ void k_stats() {   // reads g_h [Nn,Cc]
    __shared__ float ssum[Cc], ssq[Cc];
    int t = threadIdx.x;                 // 256
    if (t < Cc) { ssum[t] = 0.f; ssq[t] = 0.f; }
    __syncthreads();
    int col = t & 127;
    int rh  = t >> 7;
    float ls = 0.f, lq = 0.f;
    for (int row = blockIdx.x * 2 + rh; row < Nn; row += gridDim.x * 2) {
        float v = g_h[(size_t)row * Cc + col];
        ls += v; lq += v * v;
    }
    atomicAdd(&ssum[col], ls);
    atomicAdd(&ssq[col],  lq);
    __syncthreads();
    if (t < Cc) {
        atomicAdd(&g_stats[t],      ssum[t]);
        atomicAdd(&g_stats[Cc + t], ssq[t]);
    }
}

__global__ void k_scaleshift(const float* __restrict__ gamma, const float* __restrict__ beta) {
    int c = threadIdx.x;
    if (c < Cc) {
        float mean = g_stats[c] / (float)Nn;
        float var  = g_stats[Cc + c] / (float)Nn - mean * mean;
        float inv  = rsqrtf(var + BNEPS);
        float s    = gamma[c] * inv;
        g_scale[c] = s;
        g_shift[c] = beta[c] - mean * s;
    }
}

__global__ void k_apply(int which) {   // state = relu(h*scale+shift)
    int i = blockIdx.x * blockDim.x + threadIdx.x;   // float4 index
    if (i >= Nn * (Cc / 4)) return;
    int q = i & 31;
    float4 h  = ((const float4*)g_h)[i];
    float4 sc = *(const float4*)&g_scale[q * 4];
    float4 sh = *(const float4*)&g_shift[q * 4];
    float4 r;
    r.x = fmaxf(0.f, h.x * sc.x + sh.x);
    r.y = fmaxf(0.f, h.y * sc.y + sh.y);
    r.z = fmaxf(0.f, h.z * sc.z + sh.z);
    r.w = fmaxf(0.f, h.w * sc.w + sh.w);
    float* dstb = which ? g_state1 : g_state0;
    ((float4*)dstb)[i] = r;
}

// ---------------- aggregation: agg_mean + agg_max per state (cached) ----------------
// 4-way edge unroll with independent partial accumulators -> MLP 4 (hides L2 latency)
__global__ void k_agg(int j, const float* __restrict__ out) {
    int gw   = (blockIdx.x * blockDim.x + threadIdx.x) >> 5;
    int lane = threadIdx.x & 31;
    if (gw >= Nn) return;
    int ld;
    const float* h = state_ptr(j, out, ld);
    int e0 = g_rowptr[gw], e1 = g_rowptr[gw + 1];
    float ninf = __int_as_float(0xff800000u);
    float4 s0 = make_float4(0.f, 0.f, 0.f, 0.f), s1 = s0, s2 = s0, s3 = s0;
    float4 m0 = make_float4(ninf, ninf, ninf, ninf), m1 = m0, m2 = m0, m3 = m0;
    int e = e0;
    for (; e + 3 < e1; e += 4) {
        int a0 = g_csr[e], a1 = g_csr[e + 1], a2 = g_csr[e + 2], a3 = g_csr[e + 3];
        float4 v0 = *(const float4*)(h + (size_t)a0 * ld + lane * 4);
        float4 v1 = *(const float4*)(h + (size_t)a1 * ld + lane * 4);
        float4 v2 = *(const float4*)(h + (size_t)a2 * ld + lane * 4);
        float4 v3 = *(const float4*)(h + (size_t)a3 * ld + lane * 4);
        s0.x += v0.x; s0.y += v0.y; s0.z += v0.z; s0.w += v0.w;
        m0.x = fmaxf(m0.x, v0.x); m0.y = fmaxf(m0.y, v0.y);
        m0.z = fmaxf(m0.z, v0.z); m0.w = fmaxf(m0.w, v0.w);
        s1.x += v1.x; s1.y += v1.y; s1.z += v1.z; s1.w += v1.w;
        m1.x = fmaxf(m1.x, v1.x); m1.y = fmaxf(m1.y, v1.y);
        m1.z = fmaxf(m1.z, v1.z); m1.w = fmaxf(m1.w, v1.w);
        s2.x += v2.x; s2.y += v2.y; s2.z += v2.z; s2.w += v2.w;
        m2.x = fmaxf(m2.x, v2.x); m2.y = fmaxf(m2.y, v2.y);
        m2.z = fmaxf(m2.z, v2.z); m2.w = fmaxf(m2.w, v2.w);
        s3.x += v3.x; s3.y += v3.y; s3.z += v3.z; s3.w += v3.w;
        m3.x = fmaxf(m3.x, v3.x); m3.y = fmaxf(m3.y, v3.y);
        m3.z = fmaxf(m3.z, v3.z); m3.w = fmaxf(m3.w, v3.w);
    }
    for (; e < e1; e++) {
        int sn = g_csr[e];
        float4 v = *(const float4*)(h + (size_t)sn * ld + lane * 4);
        s0.x += v.x; s0.y += v.y; s0.z += v.z; s0.w += v.w;
        m0.x = fmaxf(m0.x, v.x); m0.y = fmaxf(m0.y, v.y);
        m0.z = fmaxf(m0.z, v.z); m0.w = fmaxf(m0.w, v.w);
    }
    float4 s = make_float4(s0.x + s1.x + s2.x + s3.x,
                           s0.y + s1.y + s2.y + s3.y,
                           s0.z + s1.z + s2.z + s3.z,
                           s0.w + s1.w + s2.w + s3.w);
    float4 m = make_float4(fmaxf(fmaxf(m0.x, m1.x), fmaxf(m2.x, m3.x)),
                           fmaxf(fmaxf(m0.y, m1.y), fmaxf(m2.y, m3.y)),
                           fmaxf(fmaxf(m0.z, m1.z), fmaxf(m2.z, m3.z)),
                           fmaxf(fmaxf(m0.w, m1.w), fmaxf(m2.w, m3.w)));
    float inv = 1.f / g_degf[gw];
    if (e0 == e1) m = make_float4(0.f, 0.f, 0.f, 0.f);
    size_t base = (size_t)j * Nn * Cc + (size_t)gw * Cc;
    ((float4*)(g_A  + base))[lane] = make_float4(s.x * inv, s.y * inv, s.z * inv, s.w * inv);
    ((float4*)(g_Mx + base))[lane] = m;
}

// ---------------- fused per-step elementwise: acc = sum_j (w1*h_j + w3*Mx_j) --------
__global__ void k_acc_step(const float* __restrict__ out, const float* __restrict__ wts,
                           int off, int k) {
    int i = blockIdx.x * blockDim.x + threadIdx.x;   // float4 index
    if (i >= Nn * (Cc / 4)) return;
    int row = i >> 5, q = i & 31;
    float4 r = make_float4(0.f, 0.f, 0.f, 0.f);
    for (int j = 0; j < k; j++) {
        float w1 = __ldg(&wts[(off + j) * 5 + 1]);
        float w3 = __ldg(&wts[(off + j) * 5 + 3]);
        int ld;
        const float* h = state_ptr(j, out, ld);
        float4 hv = *(const float4*)(h + (size_t)row * ld + q * 4);
        float4 mv = ((const float4*)(g_Mx + (size_t)j * Nn * Cc))[i];
        r.x += w1 * hv.x + w3 * mv.x;
        r.y += w1 * hv.y + w3 * mv.y;
        r.z += w1 * hv.z + w3 * mv.z;
        r.w += w1 * hv.w + w3 * mv.w;
    }
    ((float4*)g_acc)[i] = r;
}

// ---------------- combined weight stack per step ----------------
__global__ void k_wstack(const float* __restrict__ wts, const float* __restrict__ Wg,
                         const float* __restrict__ Wii, int off, int k) {
    int idx = blockIdx.x * blockDim.x + threadIdx.x;
    int tot = (k + 1) * Cc * Cc;
    if (idx >= tot) return;
    int blk = idx / (Cc * Cc);
    int rc  = idx - blk * Cc * Cc;
    if (blk < k) {
        int m = off + blk;
        g_Wstack[idx] = __ldg(&wts[m * 5 + 2]) * __ldg(&Wg[(size_t)m * Cc * Cc + rc])
                      + (1.f - ALPHAc) * __ldg(&wts[m * 5 + 4]) * __ldg(&Wii[(size_t)m * Cc * Cc + rc]);
    } else {
        float s = 0.f;
        for (int jj = 0; jj < k; jj++) {
            int m = off + jj;
            s += __ldg(&wts[m * 5 + 4]) * __ldg(&Wii[(size_t)m * Cc * Cc + rc]);
        }
        g_Wstack[idx] = ALPHAc * s;
    }
}

// ---------------- GEMM: D = [optional acc] + A(kblocks of K=128) @ B ----------------
// f32x2 packed FMA, double-buffered smem, conflict-free B fragment mapping:
// thread tx owns column PAIRS {tx*2 + 32j : j=0..3} (banks 2*tx mod 32 -> all distinct).
__global__ void __launch_bounds__(256)
k_gemm(const float* __restrict__ Aexp, const float* __restrict__ x0tail, int kblocks,
       const float* __restrict__ B, int use_acc, float* __restrict__ dstp, int ld_dst) {
    __shared__ __align__(16) float As[2][16][132];
    __shared__ __align__(16) float Bs[2][16][128];
    const int t  = threadIdx.x;            // 256
    const int tx = t & 15, ty = t >> 4;
    const int m0 = blockIdx.x * 128;
    const float* Bp = B ? B : g_Wstack;

    // packed accumulators: acc2[m][j] holds cols (tx*2 + 32j, +1)
    unsigned long long acc2[8][4];
#pragma unroll
    for (int a = 0; a < 8; a++)
#pragma unroll
        for (int b = 0; b < 4; b++) acc2[a][b] = 0ull;

    // per-thread load coordinates (same mapping as the proven R1 loader)
    const int aRow0 = (t * 2) >> 2,     aKq0 = (t * 2) & 3;
    const int aRow1 = (t * 2 + 1) >> 2, aKq1 = (t * 2 + 1) & 3;
    const int bRow0 = (t * 2) >> 5,     bC0  = (t * 2) & 31;
    const int bRow1 = (t * 2 + 1) >> 5, bC1  = (t * 2 + 1) & 31;

    const int K = kblocks * Cc;
    const int nch = K >> 4;

    float4 va0, va1, vb0, vb1;   // prefetch registers

#define LOAD_G(kk) { \
    int _kb = (kk) >> 7, _lc = (kk) & 127; \
    const float* _Ab = Aexp ? Aexp \
                     : ((_kb == kblocks - 1) ? x0tail : (g_A + (size_t)_kb * Nn * Cc)); \
    int _m0r = m0 + aRow0; \
    va0 = make_float4(0.f, 0.f, 0.f, 0.f); \
    if (_m0r < Nn) va0 = *(const float4*)(_Ab + (size_t)_m0r * Cc + _lc + aKq0 * 4); \
    int _m1r = m0 + aRow1; \
    va1 = make_float4(0.f, 0.f, 0.f, 0.f); \
    if (_m1r < Nn) va1 = *(const float4*)(_Ab + (size_t)_m1r * Cc + _lc + aKq1 * 4); \
    vb0 = *(const float4*)(Bp + (size_t)((kk) + bRow0) * Cc + bC0 * 4); \
    vb1 = *(const float4*)(Bp + (size_t)((kk) + bRow1) * Cc + bC1 * 4); }

#define STORE_S(st) { \
    As[st][aKq0 * 4 + 0][aRow0] = va0.x; \
    As[st][aKq0 * 4 + 1][aRow0] = va0.y; \
    As[st][aKq0 * 4 + 2][aRow0] = va0.z; \
    As[st][aKq0 * 4 + 3][aRow0] = va0.w; \
    As[st][aKq1 * 4 + 0][aRow1] = va1.x; \
    As[st][aKq1 * 4 + 1][aRow1] = va1.y; \
    As[st][aKq1 * 4 + 2][aRow1] = va1.z; \
    As[st][aKq1 * 4 + 3][aRow1] = va1.w; \
    *(float4*)&Bs[st][bRow0][bC0 * 4] = vb0; \
    *(float4*)&Bs[st][bRow1][bC1 * 4] = vb1; }

    LOAD_G(0);
    STORE_S(0);
    __syncthreads();

    for (int ci = 0; ci < nch; ci++) {
        int st = ci & 1;
        if (ci + 1 < nch) LOAD_G((ci + 1) << 4);
#pragma unroll
        for (int ks = 0; ks < 16; ks++) {
            float ra[8];
            unsigned long long rb2[4];
            *(float4*)&ra[0] = *(const float4*)&As[st][ks][ty * 8];
            *(float4*)&ra[4] = *(const float4*)&As[st][ks][ty * 8 + 4];
#pragma unroll
            for (int j = 0; j < 4; j++)
                rb2[j] = *(const unsigned long long*)&Bs[st][ks][tx * 2 + j * 32];
#pragma unroll
            for (int a = 0; a < 8; a++) {
                unsigned long long pa;
                PACK_DUP(pa, __float_as_uint(ra[a]));
#pragma unroll
                for (int j = 0; j < 4; j++) FFMA2(acc2[a][j], pa, rb2[j]);
            }
        }
        if (ci + 1 < nch) STORE_S(1 - st);
        __syncthreads();
    }
#undef LOAD_G
#undef STORE_S

    float* D  = dstp ? dstp : g_h;
    int    ld = dstp ? ld_dst : Cc;
#pragma unroll
    for (int a = 0; a < 8; a++) {
        int m = m0 + ty * 8 + a;
        if (m < Nn) {
#pragma unroll
            for (int j = 0; j < 4; j++) {
                int n = tx * 2 + j * 32;
                float2 v;
                v.x = __uint_as_float((uint32_t)acc2[a][j]);
                v.y = __uint_as_float((uint32_t)(acc2[a][j] >> 32));
                if (use_acc) {
                    float2 a0 = *(const float2*)(g_acc + (size_t)m * Cc + n);
                    v.x += a0.x; v.y += a0.y;
                }
                *(float2*)(D + (size_t)m * ld + n) = v;
            }
        }
    }
}

// ---------------- launch ----------------
extern "C" void kernel_launch(void* const* d_in, const int* in_sizes, int n_in,
                              void* d_out, int out_size) {
    const float* s0  = (const float*)d_in[0];
    const float* s1  = (const float*)d_in[1];
    const float* x0  = (const float*)d_in[2];
    const float* W0  = (const float*)d_in[3];
    const float* ga0 = (const float*)d_in[4];
    const float* be0 = (const float*)d_in[5];
    const float* W1  = (const float*)d_in[6];
    const float* ga1 = (const float*)d_in[7];
    const float* be1 = (const float*)d_in[8];
    const float* Wg  = (const float*)d_in[9];
    const float* Wii = (const float*)d_in[10];
    const float* wts = (const float*)d_in[11];
    const int*   ei  = (const int*)d_in[12];
    int E = in_sizes[12] / 2;
    const int* srcv = ei;
    const int* dstv = ei + E;
    float* out = (float*)d_out;

    // CSR build
    k_zero_deg<<<(Nn + 255) / 256, 256>>>();
    k_hist<<<(E + 255) / 256, 256>>>(dstv, E);
    k_scan<<<1, 1024>>>();
    k_fill<<<(E + 255) / 256, 256>>>(srcv, dstv, E);

    const int gemmBlocks = (Nn + 127) / 128;
    const int ewBlocks   = (Nn * (Cc / 4) + 255) / 256;
    const int aggBlocks  = (Nn * 32 + 255) / 256;

    // preprocess 0: g_h = s0@W0 ; BN ; relu -> g_state0
    k_gemm<<<gemmBlocks, 256>>>(s0, nullptr, 1, W0, 0, nullptr, Cc);
    k_zero_stats<<<1, 256>>>();
    k_stats<<<256, 256>>>();
    k_scaleshift<<<1, 128>>>(ga0, be0);
    k_apply<<<ewBlocks, 256>>>(0);
    // preprocess 1
    k_gemm<<<gemmBlocks, 256>>>(s1, nullptr, 1, W1, 0, nullptr, Cc);
    k_zero_stats<<<1, 256>>>();
    k_stats<<<256, 256>>>();
    k_scaleshift<<<1, 128>>>(ga1, be1);
    k_apply<<<ewBlocks, 256>>>(1);

    // cache aggregates of states 0,1
    k_agg<<<aggBlocks, 256>>>(0, out);
    k_agg<<<aggBlocks, 256>>>(1, out);

    const int offs[4] = {0, 2, 5, 9};
    for (int s = 0; s < 4; s++) {
        int k = s + 2, off = offs[s];
        int tot = (k + 1) * Cc * Cc;
        k_wstack<<<(tot + 255) / 256, 256>>>(wts, Wg, Wii, off, k);
        k_acc_step<<<ewBlocks, 256>>>(out, wts, off, k);
        // new state (2+s) written straight into out columns [s*128, s*128+128)
        k_gemm<<<gemmBlocks, 256>>>(nullptr, x0, k + 1, nullptr, 1, out + s * Cc, 4 * Cc);
        if (s < 3) k_agg<<<aggBlocks, 256>>>(2 + s, out);
    }
}

// round 17
// speedup vs baseline: 1.1336x; 1.1336x over previous
#include <cuda_runtime.h>
#include <cstdint>

#define Nn   50000
#define Cc   128
#define Emax 600000
#define ALPHAc 0.1f
#define BNEPS 1e-5f
#define WSCHUNK (6 * Cc * Cc)

// ---------------- packed dual-fp32 FMA ----------------
#define FFMA2(d, a, b) \
    asm("fma.rn.f32x2 %0, %1, %2, %0;" : "+l"(d) : "l"(a), "l"(b))
#define PACK_DUP(d, xu) \
    asm("mov.b64 %0, {%1, %1};" : "=l"(d) : "r"(xu))

// ---------------- static device scratch ----------------
__device__ int   g_deg[Nn];
__device__ float g_degf[Nn];
__device__ int   g_rowptr[Nn + 1];
__device__ int   g_cursor[Nn];
__device__ int   g_csr[Emax];
__device__ float g_state0[Nn * Cc];
__device__ float g_state1[Nn * Cc];
__device__ float g_A [5 * Nn * Cc];     // cached agg_mean per state 0..4
__device__ float g_Mx[5 * Nn * Cc];     // cached agg_max  per state 0..4
__device__ float g_acc[Nn * Cc];        // acc staging; ALSO pre1's h-buffer (disjoint in time)
__device__ float g_h  [Nn * Cc];        // pre0's h-buffer
__device__ float g_WstackAll[4 * WSCHUNK];
__device__ float g_statsA[2][2 * Cc];
__device__ float g_scaleA[2][Cc];
__device__ float g_shiftA[2][Cc];

// ---------------- small helpers ----------------
__device__ __forceinline__ const float* state_ptr(int j, const float* out, int& ld) {
    if (j == 0) { ld = Cc; return g_state0; }
    if (j == 1) { ld = Cc; return g_state1; }
    ld = 4 * Cc;
    return out + (size_t)(j - 2) * Cc;
}

// ---------------- CSR build ----------------
__global__ void k_zero_deg() {
    int i = blockIdx.x * blockDim.x + threadIdx.x;
    if (i < Nn) g_deg[i] = 0;
}

__global__ void k_hist(const int* __restrict__ dst, int E) {
    int i = blockIdx.x * blockDim.x + threadIdx.x;
    if (i < E) atomicAdd(&g_deg[dst[i]], 1);
}

__global__ void k_scan() {
    __shared__ int sh[1024];
    __shared__ int base;
    int t = threadIdx.x;
    if (t == 0) { base = 0; g_rowptr[0] = 0; }
    __syncthreads();
    for (int start = 0; start < Nn; start += 1024) {
        int i = start + t;
        int d = (i < Nn) ? g_deg[i] : 0;
        sh[t] = d;
        __syncthreads();
        for (int off = 1; off < 1024; off <<= 1) {
            int u = (t >= off) ? sh[t - off] : 0;
            __syncthreads();
            sh[t] += u;
            __syncthreads();
        }
        if (i < Nn) {
            int incl = sh[t];
            g_rowptr[i + 1] = base + incl;
            g_cursor[i]     = base + incl - d;
            g_degf[i]       = (float)(d > 1 ? d : 1);
        }
        __syncthreads();
        if (t == 0) base += sh[1023];
        __syncthreads();
    }
}

__global__ void k_fill(const int* __restrict__ src, const int* __restrict__ dst, int E) {
    int i = blockIdx.x * blockDim.x + threadIdx.x;
    if (i < E) {
        int p = atomicAdd(&g_cursor[dst[i]], 1);
        g_csr[p] = src[i];
    }
}

// ---------------- batch-norm stats / apply (parametrized by chain id) ----------------
__global__ void k_zero_stats(int which) {
    int i = threadIdx.x;
    if (i < 2 * Cc) g_statsA[which][i] = 0.f;
}

__global__ void k_stats(int which) {   // reads h-buffer (0 -> g_h, 1 -> g_acc)
    __shared__ float ssum[Cc], ssq[Cc];
    const float* h = which ? g_acc : g_h;
    int t = threadIdx.x;                 // 256
    if (t < Cc) { ssum[t] = 0.f; ssq[t] = 0.f; }
    __syncthreads();
    int col = t & 127;
    int rh  = t >> 7;
    float ls = 0.f, lq = 0.f;
    for (int row = blockIdx.x * 2 + rh; row < Nn; row += gridDim.x * 2) {
        float v = h[(size_t)row * Cc + col];
        ls += v; lq += v * v;
    }
    atomicAdd(&ssum[col], ls);
    atomicAdd(&ssq[col],  lq);
    __syncthreads();
    if (t < Cc) {
        atomicAdd(&g_statsA[which][t],      ssum[t]);
        atomicAdd(&g_statsA[which][Cc + t], ssq[t]);
    }
}

__global__ void k_scaleshift(const float* __restrict__ gamma, const float* __restrict__ beta,
                             int which) {
    int c = threadIdx.x;
    if (c < Cc) {
        float mean = g_statsA[which][c] / (float)Nn;
        float var  = g_statsA[which][Cc + c] / (float)Nn - mean * mean;
        float inv  = rsqrtf(var + BNEPS);
        float s    = gamma[c] * inv;
        g_scaleA[which][c] = s;
        g_shiftA[which][c] = beta[c] - mean * s;
    }
}

__global__ void k_apply(int which) {   // state = relu(h*scale+shift)
    int i = blockIdx.x * blockDim.x + threadIdx.x;   // float4 index
    if (i >= Nn * (Cc / 4)) return;
    int q = i & 31;
    const float* hb = which ? g_acc : g_h;
    float4 h  = ((const float4*)hb)[i];
    float4 sc = *(const float4*)&g_scaleA[which][q * 4];
    float4 sh = *(const float4*)&g_shiftA[which][q * 4];
    float4 r;
    r.x = fmaxf(0.f, h.x * sc.x + sh.x);
    r.y = fmaxf(0.f, h.y * sc.y + sh.y);
    r.z = fmaxf(0.f, h.z * sc.z + sh.z);
    r.w = fmaxf(0.f, h.w * sc.w + sh.w);
    float* dstb = which ? g_state1 : g_state0;
    ((float4*)dstb)[i] = r;
}

// ---------------- aggregation (R13-proven simple loop) ----------------
__global__ void k_agg(int j, const float* __restrict__ out) {
    int gw   = (blockIdx.x * blockDim.x + threadIdx.x) >> 5;
    int lane = threadIdx.x & 31;
    if (gw >= Nn) return;
    int ld;
    const float* h = state_ptr(j, out, ld);
    int e0 = g_rowptr[gw], e1 = g_rowptr[gw + 1];
    float ninf = __int_as_float(0xff800000u);
    float4 s = make_float4(0.f, 0.f, 0.f, 0.f);
    float4 m = make_float4(ninf, ninf, ninf, ninf);
    for (int e = e0; e < e1; e++) {
        int sn = g_csr[e];
        float4 v = *(const float4*)(h + (size_t)sn * ld + lane * 4);
        s.x += v.x; s.y += v.y; s.z += v.z; s.w += v.w;
        m.x = fmaxf(m.x, v.x); m.y = fmaxf(m.y, v.y);
        m.z = fmaxf(m.z, v.z); m.w = fmaxf(m.w, v.w);
    }
    float inv = 1.f / g_degf[gw];
    if (e0 == e1) m = make_float4(0.f, 0.f, 0.f, 0.f);
    size_t base = (size_t)j * Nn * Cc + (size_t)gw * Cc;
    ((float4*)(g_A  + base))[lane] = make_float4(s.x * inv, s.y * inv, s.z * inv, s.w * inv);
    ((float4*)(g_Mx + base))[lane] = m;
}

// ---------------- fused per-step elementwise: acc = sum_j (w1*h_j + w3*Mx_j) --------
__global__ void k_acc_step(const float* __restrict__ out, const float* __restrict__ wts,
                           int off, int k) {
    int i = blockIdx.x * blockDim.x + threadIdx.x;   // float4 index
    if (i >= Nn * (Cc / 4)) return;
    int row = i >> 5, q = i & 31;
    float4 r = make_float4(0.f, 0.f, 0.f, 0.f);
    for (int j = 0; j < k; j++) {
        float w1 = __ldg(&wts[(off + j) * 5 + 1]);
        float w3 = __ldg(&wts[(off + j) * 5 + 3]);
        int ld;
        const float* h = state_ptr(j, out, ld);
        float4 hv = *(const float4*)(h + (size_t)row * ld + q * 4);
        float4 mv = ((const float4*)(g_Mx + (size_t)j * Nn * Cc))[i];
        r.x += w1 * hv.x + w3 * mv.x;
        r.y += w1 * hv.y + w3 * mv.y;
        r.z += w1 * hv.z + w3 * mv.z;
        r.w += w1 * hv.w + w3 * mv.w;
    }
    ((float4*)g_acc)[i] = r;
}

// ---------------- combined weight stack per step (ws = buffer index) ----------------
__global__ void k_wstack(const float* __restrict__ wts, const float* __restrict__ Wg,
                         const float* __restrict__ Wii, int off, int k, int ws) {
    int idx = blockIdx.x * blockDim.x + threadIdx.x;
    int tot = (k + 1) * Cc * Cc;
    if (idx >= tot) return;
    int blk = idx / (Cc * Cc);
    int rc  = idx - blk * Cc * Cc;
    float v;
    if (blk < k) {
        int m = off + blk;
        v = __ldg(&wts[m * 5 + 2]) * __ldg(&Wg[(size_t)m * Cc * Cc + rc])
          + (1.f - ALPHAc) * __ldg(&wts[m * 5 + 4]) * __ldg(&Wii[(size_t)m * Cc * Cc + rc]);
    } else {
        float s = 0.f;
        for (int jj = 0; jj < k; jj++) {
            int m = off + jj;
            s += __ldg(&wts[m * 5 + 4]) * __ldg(&Wii[(size_t)m * Cc * Cc + rc]);
        }
        v = ALPHAc * s;
    }
    g_WstackAll[ws * WSCHUNK + idx] = v;
}

// ---------------- GEMM: D = [optional acc] + A(kblocks of K=128) @ B ----------------
// f32x2 packed FMA, double-buffered smem, conflict-free B fragment mapping.
// B source: explicit pointer, else g_WstackAll chunk wsel. Dst: dsel 0=g_h, 1=g_acc, 2=dstp.
__global__ void __launch_bounds__(256)
k_gemm(const float* __restrict__ Aexp, const float* __restrict__ x0tail, int kblocks,
       const float* __restrict__ B, int wsel, int use_acc,
       int dsel, float* __restrict__ dstp, int ld_dst) {
    __shared__ __align__(16) float As[2][16][132];
    __shared__ __align__(16) float Bs[2][16][128];
    const int t  = threadIdx.x;            // 256
    const int tx = t & 15, ty = t >> 4;
    const int m0 = blockIdx.x * 128;
    const float* Bp = B ? B : (g_WstackAll + (size_t)wsel * WSCHUNK);

    unsigned long long acc2[8][4];
#pragma unroll
    for (int a = 0; a < 8; a++)
#pragma unroll
        for (int b = 0; b < 4; b++) acc2[a][b] = 0ull;

    const int aRow0 = (t * 2) >> 2,     aKq0 = (t * 2) & 3;
    const int aRow1 = (t * 2 + 1) >> 2, aKq1 = (t * 2 + 1) & 3;
    const int bRow0 = (t * 2) >> 5,     bC0  = (t * 2) & 31;
    const int bRow1 = (t * 2 + 1) >> 5, bC1  = (t * 2 + 1) & 31;

    const int K = kblocks * Cc;
    const int nch = K >> 4;

    float4 va0, va1, vb0, vb1;

#define LOAD_G(kk) { \
    int _kb = (kk) >> 7, _lc = (kk) & 127; \
    const float* _Ab = Aexp ? Aexp \
                     : ((_kb == kblocks - 1) ? x0tail : (g_A + (size_t)_kb * Nn * Cc)); \
    int _m0r = m0 + aRow0; \
    va0 = make_float4(0.f, 0.f, 0.f, 0.f); \
    if (_m0r < Nn) va0 = *(const float4*)(_Ab + (size_t)_m0r * Cc + _lc + aKq0 * 4); \
    int _m1r = m0 + aRow1; \
    va1 = make_float4(0.f, 0.f, 0.f, 0.f); \
    if (_m1r < Nn) va1 = *(const float4*)(_Ab + (size_t)_m1r * Cc + _lc + aKq1 * 4); \
    vb0 = *(const float4*)(Bp + (size_t)((kk) + bRow0) * Cc + bC0 * 4); \
    vb1 = *(const float4*)(Bp + (size_t)((kk) + bRow1) * Cc + bC1 * 4); }

#define STORE_S(st) { \
    As[st][aKq0 * 4 + 0][aRow0] = va0.x; \
    As[st][aKq0 * 4 + 1][aRow0] = va0.y; \
    As[st][aKq0 * 4 + 2][aRow0] = va0.z; \
    As[st][aKq0 * 4 + 3][aRow0] = va0.w; \
    As[st][aKq1 * 4 + 0][aRow1] = va1.x; \
    As[st][aKq1 * 4 + 1][aRow1] = va1.y; \
    As[st][aKq1 * 4 + 2][aRow1] = va1.z; \
    As[st][aKq1 * 4 + 3][aRow1] = va1.w; \
    *(float4*)&Bs[st][bRow0][bC0 * 4] = vb0; \
    *(float4*)&Bs[st][bRow1][bC1 * 4] = vb1; }

    LOAD_G(0);
    STORE_S(0);
    __syncthreads();

    for (int ci = 0; ci < nch; ci++) {
        int st = ci & 1;
        if (ci + 1 < nch) LOAD_G((ci + 1) << 4);
#pragma unroll
        for (int ks = 0; ks < 16; ks++) {
            float ra[8];
            unsigned long long rb2[4];
            *(float4*)&ra[0] = *(const float4*)&As[st][ks][ty * 8];
            *(float4*)&ra[4] = *(const float4*)&As[st][ks][ty * 8 + 4];
#pragma unroll
            for (int j = 0; j < 4; j++)
                rb2[j] = *(const unsigned long long*)&Bs[st][ks][tx * 2 + j * 32];
#pragma unroll
            for (int a = 0; a < 8; a++) {
                unsigned long long pa;
                PACK_DUP(pa, __float_as_uint(ra[a]));
#pragma unroll
                for (int j = 0; j < 4; j++) FFMA2(acc2[a][j], pa, rb2[j]);
            }
        }
        if (ci + 1 < nch) STORE_S(1 - st);
        __syncthreads();
    }
#undef LOAD_G
#undef STORE_S

    float* D  = (dsel == 0) ? g_h : (dsel == 1) ? g_acc : dstp;
    int    ld = (dsel == 2) ? ld_dst : Cc;
#pragma unroll
    for (int a = 0; a < 8; a++) {
        int m = m0 + ty * 8 + a;
        if (m < Nn) {
#pragma unroll
            for (int j = 0; j < 4; j++) {
                int n = tx * 2 + j * 32;
                float2 v;
                v.x = __uint_as_float((uint32_t)acc2[a][j]);
                v.y = __uint_as_float((uint32_t)(acc2[a][j] >> 32));
                if (use_acc) {
                    float2 a0 = *(const float2*)(g_acc + (size_t)m * Cc + n);
                    v.x += a0.x; v.y += a0.y;
                }
                *(float2*)(D + (size_t)m * ld + n) = v;
            }
        }
    }
}

// ---------------- launch ----------------
extern "C" void kernel_launch(void* const* d_in, const int* in_sizes, int n_in,
                              void* d_out, int out_size) {
    const float* s0  = (const float*)d_in[0];
    const float* s1  = (const float*)d_in[1];
    const float* x0  = (const float*)d_in[2];
    const float* W0  = (const float*)d_in[3];
    const float* ga0 = (const float*)d_in[4];
    const float* be0 = (const float*)d_in[5];
    const float* W1  = (const float*)d_in[6];
    const float* ga1 = (const float*)d_in[7];
    const float* be1 = (const float*)d_in[8];
    const float* Wg  = (const float*)d_in[9];
    const float* Wii = (const float*)d_in[10];
    const float* wts = (const float*)d_in[11];
    const int*   ei  = (const int*)d_in[12];
    int E = in_sizes[12] / 2;
    const int* srcv = ei;
    const int* dstv = ei + E;
    float* out = (float*)d_out;

    // streams/events created on first (uncaptured) call; no device memory involved
    static cudaStream_t sA = nullptr, sB = nullptr, sC = nullptr;
    static cudaEvent_t  eRoot = nullptr, eA = nullptr, eB = nullptr, eC = nullptr;
    if (sA == nullptr) {
        cudaStreamCreateWithFlags(&sA, cudaStreamNonBlocking);
        cudaStreamCreateWithFlags(&sB, cudaStreamNonBlocking);
        cudaStreamCreateWithFlags(&sC, cudaStreamNonBlocking);
        cudaEventCreateWithFlags(&eRoot, cudaEventDisableTiming);
        cudaEventCreateWithFlags(&eA, cudaEventDisableTiming);
        cudaEventCreateWithFlags(&eB, cudaEventDisableTiming);
        cudaEventCreateWithFlags(&eC, cudaEventDisableTiming);
    }

    const int gemmBlocks = (Nn + 127) / 128;
    const int ewBlocks   = (Nn * (Cc / 4) + 255) / 256;
    const int aggBlocks  = (Nn * 32 + 255) / 256;
    const int offs[4] = {0, 2, 5, 9};

    // ---- fork ----
    cudaEventRecord(eRoot, 0);
    cudaStreamWaitEvent(sA, eRoot, 0);
    cudaStreamWaitEvent(sB, eRoot, 0);
    cudaStreamWaitEvent(sC, eRoot, 0);

    // stream A: CSR build
    k_zero_deg<<<(Nn + 255) / 256, 256, 0, sA>>>();
    k_hist<<<(E + 255) / 256, 256, 0, sA>>>(dstv, E);
    k_scan<<<1, 1024, 0, sA>>>();
    k_fill<<<(E + 255) / 256, 256, 0, sA>>>(srcv, dstv, E);
    cudaEventRecord(eA, sA);

    // stream B: preprocess 0 (h-buffer g_h, stats set 0)
    k_gemm<<<gemmBlocks, 256, 0, sB>>>(s0, nullptr, 1, W0, 0, 0, 0, nullptr, Cc);
    k_zero_stats<<<1, 256, 0, sB>>>(0);
    k_stats<<<256, 256, 0, sB>>>(0);
    k_scaleshift<<<1, 128, 0, sB>>>(ga0, be0, 0);
    k_apply<<<ewBlocks, 256, 0, sB>>>(0);
    cudaEventRecord(eB, sB);

    // stream C: preprocess 1 (h-buffer g_acc, stats set 1)
    k_gemm<<<gemmBlocks, 256, 0, sC>>>(s1, nullptr, 1, W1, 0, 0, 1, nullptr, Cc);
    k_zero_stats<<<1, 256, 0, sC>>>(1);
    k_stats<<<256, 256, 0, sC>>>(1);
    k_scaleshift<<<1, 128, 0, sC>>>(ga1, be1, 1);
    k_apply<<<ewBlocks, 256, 0, sC>>>(1);
    cudaEventRecord(eC, sC);

    // default stream: all four weight stacks (independent of everything above)
    for (int s = 0; s < 4; s++) {
        int k = s + 2;
        int tot = (k + 1) * Cc * Cc;
        k_wstack<<<(tot + 255) / 256, 256>>>(wts, Wg, Wii, offs[s], k, s);
    }

    // ---- join ----
    cudaStreamWaitEvent(0, eA, 0);
    cudaStreamWaitEvent(0, eB, 0);
    cudaStreamWaitEvent(0, eC, 0);

    // cache aggregates of states 0,1
    k_agg<<<aggBlocks, 256>>>(0, out);
    k_agg<<<aggBlocks, 256>>>(1, out);

    for (int s = 0; s < 4; s++) {
        int k = s + 2, off = offs[s];
        k_acc_step<<<ewBlocks, 256>>>(out, wts, off, k);
        // new state (2+s) written straight into out columns [s*128, s*128+128)
        k_gemm<<<gemmBlocks, 256>>>(nullptr, x0, k + 1, nullptr, s, 1,
                                    2, out + s * Cc, 4 * Cc);
        if (s < 3) k_agg<<<aggBlocks, 256>>>(2 + s, out);
    }
}